// round 1
// baseline (speedup 1.0000x reference)
#include <cuda_runtime.h>
#include <cstdint>

// Problem constants
#define BATCH 8
#define C     192
#define CQ    32
#define NPIX  16384
#define SUB   32      // pixels per subtile
#define NSUBT 8       // subtiles per block
#define TILE  (SUB*NSUBT)     // 256 pixels per block
#define NPARTS (NPIX/TILE)    // 64 blocks per batch
#define KC    32      // k-chunk for Wv staging

// ---------------- deterministic scratch (no allocations, no atomics) ----------
__device__ float g_part_mat [BATCH*NPARTS*CQ*C];   // 12.6 MB
__device__ float g_part_vsum[BATCH*NPARTS*C];
__device__ float g_part_ksum[BATCH*NPARTS*CQ];
__device__ float g_mat [BATCH*CQ*C];
__device__ float g_vsum[BATCH*C];
__device__ float g_ksum[BATCH*CQ];

// ---------------- packed f32x2 helpers (sm_103a: FFMA2 doubles FP32 rate) -----
__device__ __forceinline__ unsigned long long pack2dup(float x) {
    unsigned long long r;
    asm("mov.b64 %0, {%1, %1};" : "=l"(r) : "f"(x));
    return r;
}
__device__ __forceinline__ void unpack2(unsigned long long v, float& lo, float& hi) {
    asm("mov.b64 {%0, %1}, %2;" : "=f"(lo), "=f"(hi) : "l"(v));
}
__device__ __forceinline__ unsigned long long ffma2(unsigned long long a,
                                                    unsigned long long b,
                                                    unsigned long long c) {
    unsigned long long d;
    asm("fma.rn.f32x2 %0, %1, %2, %3;" : "=l"(d) : "l"(a), "l"(b), "l"(c));
    return d;
}

// ---------------- smem layouts (floats) ----------------
// pass1: xs[192*32] vt[32*194] wv[32*194] kn[32*32] ksq[256] invn[32] wkpart[32]
//        ksuml[32] vsuml[192]
#define P1_XS     0
#define P1_VT     6144
#define P1_WV     12352
#define P1_KN     18560
#define P1_KSQ    19584
#define P1_INVN   19840
#define P1_WKP    19872
#define P1_KSUML  19904
#define P1_VSUML  19936
#define P1_TOT    20128
#define SMEM1_BYTES (P1_TOT*4)

#define P2_XS     0
#define P2_MATS   6144
#define P2_QN     12288
#define P2_QSQ    13312
#define P2_INVN   13568
#define P2_SDP    13600
#define P2_TS     13856
#define P2_KSUM   13888
#define P2_VSUM   13920
#define P2_TOT    14112
#define SMEM2_BYTES (P2_TOT*4)

// =============================================================================
// Pass 1: K-proj + normalize, V-proj, reduce into per-block partials of
//         ksum[32], vsum[192], matrix[32x192]
// =============================================================================
__global__ __launch_bounds__(256, 2)
void pass1_kernel(const float* __restrict__ x, const float* __restrict__ x1,
                  const float* __restrict__ Wk, const float* __restrict__ bk,
                  const float* __restrict__ Wv, const float* __restrict__ bv)
{
    extern __shared__ float sm[];
    float* xs    = sm + P1_XS;
    float* vt    = sm + P1_VT;     // [t][c] stride 194
    float* wv    = sm + P1_WV;     // [kk][c] stride 194
    float* kn    = sm + P1_KN;     // [m][t] stride 32
    float* ksq   = sm + P1_KSQ;
    float* invn  = sm + P1_INVN;
    float* wkp   = sm + P1_WKP;
    float* ksuml = sm + P1_KSUML;
    float* vsuml = sm + P1_VSUML;

    const int tid  = threadIdx.x;
    const int lane = tid & 31;
    const int wgrp = tid >> 5;     // 0..7
    const int b    = blockIdx.y;
    const int part = blockIdx.x;

    if (tid < 32)  ksuml[tid] = 0.f;
    if (tid < 192) vsuml[tid] = 0.f;

    // matrix accumulators: m = wgrp + 8*i, c-pair = (2*lane + 64*j, +1)
    unsigned long long macc[4][3];
#pragma unroll
    for (int i = 0; i < 4; i++)
#pragma unroll
        for (int j = 0; j < 3; j++) macc[i][j] = 0ull;

    const float* x1b = x1 + (size_t)b * C * NPIX;
    const float* xb  = x  + (size_t)b * C * NPIX;

    for (int s = 0; s < NSUBT; s++) {
        const int n0 = part * TILE + s * SUB;
        __syncthreads();   // protect xs/kn/vt reuse across subtiles

        // ---- load x1 subtile: xs[c][t] ----
#pragma unroll
        for (int i = 0; i < 24; i++) {
            int c = wgrp + 8 * i;
            xs[c * 32 + lane] = x1b[(size_t)c * NPIX + n0 + lane];
        }
        __syncthreads();

        // ---- K projection: m = wgrp + 8*u, t = lane ----
        float acc[4];
#pragma unroll
        for (int u = 0; u < 4; u++) acc[u] = bk[wgrp + 8 * u];
        for (int k = 0; k < C; k++) {
            float xv = xs[k * 32 + lane];
#pragma unroll
            for (int u = 0; u < 4; u++)
                acc[u] = fmaf(Wk[(wgrp + 8 * u) * C + k], xv, acc[u]);
        }
        ksq[wgrp * 32 + lane] =
            acc[0]*acc[0] + acc[1]*acc[1] + acc[2]*acc[2] + acc[3]*acc[3];
        __syncthreads();
        if (tid < 32) {
            float tot = 0.f;
#pragma unroll
            for (int g = 0; g < 8; g++) tot += ksq[g * 32 + tid];
            invn[tid] = rsqrtf(tot);
        }
        __syncthreads();
        {
            float inv = invn[lane];
#pragma unroll
            for (int u = 0; u < 4; u++) {
                float kv = acc[u] * inv;
                kn[(wgrp + 8 * u) * 32 + lane] = kv;
                // deterministic ksum: warp shuffle over lanes (=pixels)
#pragma unroll
                for (int off = 16; off; off >>= 1)
                    kv += __shfl_down_sync(0xffffffffu, kv, off);
                if (lane == 0) wkp[wgrp * 4 + u] = kv;
            }
        }
        __syncthreads();
        if (tid < 32) ksuml[tid] += wkp[(tid & 7) * 4 + (tid >> 3)];

        // ---- load x subtile (overwrite xs) ----
#pragma unroll
        for (int i = 0; i < 24; i++) {
            int c = wgrp + 8 * i;
            xs[c * 32 + lane] = xb[(size_t)c * NPIX + n0 + lane];
        }

        // ---- V projection (packed over c-pairs): t=lane, c0 = wgrp*24 ----
        unsigned long long vacc[12];
        const int c0 = wgrp * 24;
#pragma unroll
        for (int j = 0; j < 12; j++)
            vacc[j] = *(const unsigned long long*)&bv[c0 + 2 * j];

        for (int kc0 = 0; kc0 < C; kc0 += KC) {
            __syncthreads();   // prev chunk consumed; also makes xs visible
            // stage Wv[:, kc0:kc0+32] -> wv[kk][c] (coalesced global reads)
#pragma unroll
            for (int i = 0; i < 24; i++) {
                int idx = tid + i * 256;
                int cc = idx >> 5;
                int kk = idx & 31;
                wv[kk * 194 + cc] = Wv[(size_t)cc * C + kc0 + kk];
            }
            __syncthreads();
#pragma unroll 8
            for (int kk = 0; kk < KC; kk++) {
                unsigned long long xv2 = pack2dup(xs[(kc0 + kk) * 32 + lane]);
#pragma unroll
                for (int j = 0; j < 12; j++) {
                    unsigned long long w2 =
                        *(const unsigned long long*)&wv[kk * 194 + c0 + 2 * j];
                    vacc[j] = ffma2(w2, xv2, vacc[j]);
                }
            }
        }
        // write V tile: vt[t][c], stride 194
#pragma unroll
        for (int j = 0; j < 12; j++)
            *(unsigned long long*)&vt[lane * 194 + c0 + 2 * j] = vacc[j];
        __syncthreads();

        // ---- vsum (single owner per c: deterministic) ----
        if (tid < 192) {
            float sv = 0.f;
#pragma unroll
            for (int t = 0; t < SUB; t++) sv += vt[t * 194 + tid];
            vsuml[tid] += sv;
        }

        // ---- matrix += Kn * V^T  (packed over c-pairs) ----
#pragma unroll 2
        for (int t = 0; t < SUB; t++) {
            unsigned long long kd[4];
#pragma unroll
            for (int i = 0; i < 4; i++)
                kd[i] = pack2dup(kn[(wgrp + 8 * i) * 32 + t]);
#pragma unroll
            for (int j = 0; j < 3; j++) {
                unsigned long long v2 =
                    *(const unsigned long long*)&vt[t * 194 + 2 * lane + 64 * j];
#pragma unroll
                for (int i = 0; i < 4; i++)
                    macc[i][j] = ffma2(kd[i], v2, macc[i][j]);
            }
        }
    }

    __syncthreads();
    // ---- write per-block partials (deterministic, no atomics) ----
    float* pm = g_part_mat + ((size_t)b * NPARTS + part) * CQ * C;
#pragma unroll
    for (int i = 0; i < 4; i++)
#pragma unroll
        for (int j = 0; j < 3; j++)
            *(unsigned long long*)&pm[(wgrp + 8 * i) * C + 2 * lane + 64 * j] =
                macc[i][j];
    if (tid < 192) g_part_vsum[((size_t)b * NPARTS + part) * C  + tid] = vsuml[tid];
    if (tid < 32)  g_part_ksum[((size_t)b * NPARTS + part) * CQ + tid] = ksuml[tid];
}

// =============================================================================
// Reduce partials -> g_mat, g_vsum, g_ksum (fixed order => deterministic)
// =============================================================================
__global__ void reduce_kernel()
{
    const int MATN = BATCH * CQ * C;   // 49152
    const int VSN  = BATCH * C;        // 1536
    const int KSN  = BATCH * CQ;       // 256
    int idx = blockIdx.x * blockDim.x + threadIdx.x;
    if (idx < MATN) {
        int bb = idx / (CQ * C), r = idx % (CQ * C);
        const float* p = g_part_mat + (size_t)bb * NPARTS * CQ * C + r;
        float sv = 0.f;
#pragma unroll 8
        for (int q = 0; q < NPARTS; q++) sv += p[(size_t)q * CQ * C];
        g_mat[idx] = sv;
    } else if (idx < MATN + VSN) {
        int k = idx - MATN;
        int bb = k / C, r = k % C;
        const float* p = g_part_vsum + (size_t)bb * NPARTS * C + r;
        float sv = 0.f;
#pragma unroll 8
        for (int q = 0; q < NPARTS; q++) sv += p[q * C];
        g_vsum[k] = sv;
    } else if (idx < MATN + VSN + KSN) {
        int k = idx - MATN - VSN;
        int bb = k / CQ, r = k % CQ;
        const float* p = g_part_ksum + (size_t)bb * NPARTS * CQ + r;
        float sv = 0.f;
#pragma unroll 8
        for (int q = 0; q < NPARTS; q++) sv += p[q * CQ];
        g_ksum[k] = sv;
    }
}

// =============================================================================
// Pass 2: Q-proj + normalize, tailor_sum, out = gamma*ts*(vsum + Qn·matrix)
// =============================================================================
__global__ __launch_bounds__(256)
void pass2_kernel(const float* __restrict__ x1,
                  const float* __restrict__ Wq, const float* __restrict__ bq,
                  const float* __restrict__ gamma, float* __restrict__ out)
{
    extern __shared__ float sm[];
    float* xs     = sm + P2_XS;
    float* mats   = sm + P2_MATS;   // [m][c] stride 192
    float* qn     = sm + P2_QN;     // [m][t] stride 32
    float* qsq    = sm + P2_QSQ;
    float* invn   = sm + P2_INVN;
    float* sdp    = sm + P2_SDP;
    float* ts_s   = sm + P2_TS;
    float* ksum_s = sm + P2_KSUM;
    float* vsum_s = sm + P2_VSUM;

    const int tid  = threadIdx.x;
    const int lane = tid & 31;
    const int wgrp = tid >> 5;
    const int b    = blockIdx.y;
    const int part = blockIdx.x;
    const float gm = gamma[0];

#pragma unroll
    for (int i = 0; i < 24; i++) {
        int idx = tid + i * 256;
        mats[idx] = g_mat[(size_t)b * CQ * C + idx];
    }
    if (tid < 32)  ksum_s[tid] = g_ksum[b * CQ + tid] + 1e-6f;
    if (tid < 192) vsum_s[tid] = g_vsum[b * C + tid];

    const float* x1b = x1 + (size_t)b * C * NPIX;
    float* outb = out + (size_t)b * C * NPIX;

    for (int s = 0; s < NSUBT; s++) {
        const int n0 = part * TILE + s * SUB;
        __syncthreads();
#pragma unroll
        for (int i = 0; i < 24; i++) {
            int c = wgrp + 8 * i;
            xs[c * 32 + lane] = x1b[(size_t)c * NPIX + n0 + lane];
        }
        __syncthreads();

        // ---- Q projection ----
        float acc[4];
#pragma unroll
        for (int u = 0; u < 4; u++) acc[u] = bq[wgrp + 8 * u];
        for (int k = 0; k < C; k++) {
            float xv = xs[k * 32 + lane];
#pragma unroll
            for (int u = 0; u < 4; u++)
                acc[u] = fmaf(Wq[(wgrp + 8 * u) * C + k], xv, acc[u]);
        }
        qsq[wgrp * 32 + lane] =
            acc[0]*acc[0] + acc[1]*acc[1] + acc[2]*acc[2] + acc[3]*acc[3];
        __syncthreads();
        if (tid < 32) {
            float tot = 0.f;
#pragma unroll
            for (int g = 0; g < 8; g++) tot += qsq[g * 32 + tid];
            invn[tid] = rsqrtf(tot);
        }
        __syncthreads();
        {
            float inv = invn[lane];
            float sd = 0.f;
#pragma unroll
            for (int u = 0; u < 4; u++) {
                float q = acc[u] * inv;
                qn[(wgrp + 8 * u) * 32 + lane] = q;
                sd = fmaf(q, ksum_s[wgrp + 8 * u], sd);
            }
            sdp[wgrp * 32 + lane] = sd;
        }
        __syncthreads();
        if (tid < 32) {
            float tot = 0.f;
#pragma unroll
            for (int g = 0; g < 8; g++) tot += sdp[g * 32 + tid];
            ts_s[tid] = 1.0f / (16384.0f + tot);
        }
        __syncthreads();

        // ---- out gemm: t = lane, c0 = wgrp*24, packed over c-pairs ----
        unsigned long long oacc[12];
        const int c0 = wgrp * 24;
#pragma unroll
        for (int j = 0; j < 12; j++)
            oacc[j] = *(const unsigned long long*)&vsum_s[c0 + 2 * j];
#pragma unroll 4
        for (int m = 0; m < CQ; m++) {
            unsigned long long q2 = pack2dup(qn[m * 32 + lane]);
#pragma unroll
            for (int j = 0; j < 12; j++) {
                unsigned long long w2 =
                    *(const unsigned long long*)&mats[m * C + c0 + 2 * j];
                oacc[j] = ffma2(w2, q2, oacc[j]);
            }
        }
        const float gt = gm * ts_s[lane];
#pragma unroll
        for (int j = 0; j < 12; j++) {
            float lo, hi;
            unpack2(oacc[j], lo, hi);
            outb[(size_t)(c0 + 2 * j)     * NPIX + n0 + lane] = gt * lo;
            outb[(size_t)(c0 + 2 * j + 1) * NPIX + n0 + lane] = gt * hi;
        }
    }
}

// =============================================================================
extern "C" void kernel_launch(void* const* d_in, const int* in_sizes, int n_in,
                              void* d_out, int out_size)
{
    const float* x     = (const float*)d_in[0];
    const float* x1    = (const float*)d_in[1];
    const float* Wq    = (const float*)d_in[2];
    const float* bq    = (const float*)d_in[3];
    const float* Wk    = (const float*)d_in[4];
    const float* bk    = (const float*)d_in[5];
    const float* Wv    = (const float*)d_in[6];
    const float* bv    = (const float*)d_in[7];
    const float* gamma = (const float*)d_in[8];
    float* out = (float*)d_out;

    cudaFuncSetAttribute(pass1_kernel,
                         cudaFuncAttributeMaxDynamicSharedMemorySize, SMEM1_BYTES);
    cudaFuncSetAttribute(pass2_kernel,
                         cudaFuncAttributeMaxDynamicSharedMemorySize, SMEM2_BYTES);

    dim3 grid(NPARTS, BATCH);
    pass1_kernel<<<grid, 256, SMEM1_BYTES>>>(x, x1, Wk, bk, Wv, bv);

    const int RED = BATCH * CQ * C + BATCH * C + BATCH * CQ;
    reduce_kernel<<<(RED + 255) / 256, 256>>>();

    pass2_kernel<<<grid, 256, SMEM2_BYTES>>>(x1, Wq, bq, gamma, out);
}

// round 2
// speedup vs baseline: 1.7371x; 1.7371x over previous
#include <cuda_runtime.h>
#include <cstdint>

// Problem constants
#define BATCH 8
#define C     192
#define CQ    32
#define NPIX  16384
#define SUB   64              // pixels per subtile (2 per thread)
#define NSUBT 4               // subtiles per block
#define TILE  (SUB*NSUBT)     // 256 pixels per block
#define NPARTS (NPIX/TILE)    // 64 blocks per batch
#define KC    32              // k-chunk for Wv staging

typedef unsigned long long u64;

// ---------------- deterministic scratch (no allocations, no atomics) ----------
__device__ float g_part_mat [BATCH*NPARTS*CQ*C];
__device__ float g_part_vsum[BATCH*NPARTS*C];
__device__ float g_part_ksum[BATCH*NPARTS*CQ];
__device__ float g_mat [BATCH*CQ*C];
__device__ float g_vsum[BATCH*C];
__device__ float g_ksum[BATCH*CQ];

// ---------------- packed f32x2 helpers ----------------
__device__ __forceinline__ u64 pack2dup(float x) {
    u64 r; asm("mov.b64 %0, {%1, %1};" : "=l"(r) : "f"(x)); return r;
}
__device__ __forceinline__ u64 pack2(float a, float b) {
    u64 r; asm("mov.b64 %0, {%1, %2};" : "=l"(r) : "f"(a), "f"(b)); return r;
}
__device__ __forceinline__ void unpack2(u64 v, float& lo, float& hi) {
    asm("mov.b64 {%0, %1}, %2;" : "=f"(lo), "=f"(hi) : "l"(v));
}
__device__ __forceinline__ u64 ffma2(u64 a, u64 b, u64 c) {
    u64 d; asm("fma.rn.f32x2 %0, %1, %2, %3;" : "=l"(d) : "l"(a), "l"(b), "l"(c));
    return d;
}
__device__ __forceinline__ u64 fmul2(u64 a, u64 b) {
    u64 d; asm("mul.rn.f32x2 %0, %1, %2;" : "=l"(d) : "l"(a), "l"(b)); return d;
}
__device__ __forceinline__ u64 fadd2(u64 a, u64 b) {
    u64 d; asm("add.rn.f32x2 %0, %1, %2;" : "=l"(d) : "l"(a), "l"(b)); return d;
}

// ---------------- smem layouts (float offsets) ----------------
// pass1
#define P1_BUF0   0       // xs [192][64] (12288) or vt [64][194] (12416)
#define P1_WV     12416   // [32][194] = 6208
#define P1_WK     18624   // [32][192] = 6144
#define P1_KN     24768   // [32][64]  = 2048
#define P1_KSQ    26816   // [8][64]   = 512
#define P1_INVN   27328   // [64]
#define P1_WKP    27392   // [32]
#define P1_KSUML  27424   // [32]
#define P1_VSUML  27456   // [192]
#define P1_TOT    27648
#define SMEM1_BYTES (P1_TOT*4)

// pass2
#define P2_XS     0       // [192][64] = 12288
#define P2_MATS   12288   // [32][192] = 6144
#define P2_QN     18432   // [32][64]  = 2048
#define P2_QSQ    20480   // [8][64]   = 512
#define P2_INVN   20992   // [64]
#define P2_SDP    21056   // [8][64]   = 512
#define P2_TS     21568   // [64]
#define P2_KSUM   21632   // [32]
#define P2_VSUM   21664   // [192]
#define P2_TOT    21856
#define SMEM2_BYTES (P2_TOT*4)

// =============================================================================
// Pass 1
// =============================================================================
__global__ __launch_bounds__(256, 2)
void pass1_kernel(const float* __restrict__ x, const float* __restrict__ x1,
                  const float* __restrict__ Wk, const float* __restrict__ bk,
                  const float* __restrict__ Wv, const float* __restrict__ bv)
{
    extern __shared__ float sm[];
    float* buf0  = sm + P1_BUF0;
    float* wv    = sm + P1_WV;
    float* wk    = sm + P1_WK;
    float* kn    = sm + P1_KN;
    float* ksq   = sm + P1_KSQ;
    float* invn  = sm + P1_INVN;
    float* wkp   = sm + P1_WKP;
    float* ksuml = sm + P1_KSUML;
    float* vsuml = sm + P1_VSUML;

    const int tid  = threadIdx.x;
    const int lane = tid & 31;
    const int wgrp = tid >> 5;
    const int b    = blockIdx.y;
    const int part = blockIdx.x;
    const int pl   = 2 * lane;       // pixel-pair base within subtile
    const int c0   = wgrp * 24;      // channel block for V

    // stage Wk once per block (row-major copy, coalesced + conflict-free)
#pragma unroll
    for (int i = 0; i < 24; i++) wk[tid + i * 256] = Wk[tid + i * 256];
    if (tid < 32)  ksuml[tid] = 0.f;
    if (tid < 192) vsuml[tid] = 0.f;

    // matrix accumulators: m = wgrp + 8*i, ch-pair = 2*lane + 64*j
    u64 macc[4][3];
#pragma unroll
    for (int i = 0; i < 4; i++)
#pragma unroll
        for (int j = 0; j < 3; j++) macc[i][j] = 0ull;

    const float* x1b = x1 + (size_t)b * C * NPIX;
    const float* xb  = x  + (size_t)b * C * NPIX;

    for (int s = 0; s < NSUBT; s++) {
        const int n0 = part * TILE + s * SUB;
        __syncthreads();   // protect buf0(vt)/kn from previous subtile readers

        // ---- load x1 subtile: buf0[c][t] (float2 per thread) ----
#pragma unroll
        for (int i = 0; i < 24; i++) {
            int c = wgrp + 8 * i;
            *(float2*)&buf0[c * 64 + pl] =
                *(const float2*)&x1b[(size_t)c * NPIX + n0 + pl];
        }
        __syncthreads();

        // ---- K projection (packed over pixel pair) ----
        u64 acc2[4];
#pragma unroll
        for (int u = 0; u < 4; u++) acc2[u] = pack2dup(bk[wgrp + 8 * u]);
#pragma unroll 8
        for (int k = 0; k < C; k++) {
            u64 xp = *(const u64*)&buf0[k * 64 + pl];
#pragma unroll
            for (int u = 0; u < 4; u++)
                acc2[u] = ffma2(xp, pack2dup(wk[(wgrp + 8 * u) * 192 + k]), acc2[u]);
        }
        // per-pixel sum of squares (packed)
        {
            u64 sq = fmul2(acc2[0], acc2[0]);
#pragma unroll
            for (int u = 1; u < 4; u++) sq = ffma2(acc2[u], acc2[u], sq);
            *(u64*)&ksq[wgrp * 64 + pl] = sq;
        }
        __syncthreads();
        if (tid < 64) {
            float tot = 0.f;
#pragma unroll
            for (int g = 0; g < 8; g++) tot += ksq[g * 64 + tid];
            invn[tid] = rsqrtf(tot);
        }
        __syncthreads();
        {
            u64 inv2 = *(const u64*)&invn[pl];
#pragma unroll
            for (int u = 0; u < 4; u++) {
                u64 kp = fmul2(acc2[u], inv2);
                *(u64*)&kn[(wgrp + 8 * u) * 64 + pl] = kp;
                float lo, hi; unpack2(kp, lo, hi);
                float sv = lo + hi;
#pragma unroll
                for (int off = 16; off; off >>= 1)
                    sv += __shfl_down_sync(0xffffffffu, sv, off);
                if (lane == 0) wkp[wgrp * 4 + u] = sv;
            }
        }
        __syncthreads();
        if (tid < 32) ksuml[tid] += wkp[(tid & 7) * 4 + (tid >> 3)];

        // ---- load x subtile (overwrite xs region) ----
        // (safe: all xs(x1) reads completed before the ksq __syncthreads)
#pragma unroll
        for (int i = 0; i < 24; i++) {
            int c = wgrp + 8 * i;
            *(float2*)&buf0[c * 64 + pl] =
                *(const float2*)&xb[(size_t)c * NPIX + n0 + pl];
        }

        // ---- V projection: 2 px x 12 ch-pairs per thread ----
        u64 vacc[2][12];
#pragma unroll
        for (int j = 0; j < 12; j++) {
            float2 bvv = *(const float2*)&bv[c0 + 2 * j];
            u64 bp = pack2(bvv.x, bvv.y);
            vacc[0][j] = bp; vacc[1][j] = bp;
        }
        for (int kc0 = 0; kc0 < C; kc0 += KC) {
            __syncthreads();   // prev wv chunk consumed; first iter: xs visible
#pragma unroll
            for (int i = 0; i < 24; i++) {
                int idx = tid + i * 256;
                int cc = idx >> 5, kk = idx & 31;
                wv[kk * 194 + cc] = Wv[(size_t)cc * C + kc0 + kk];
            }
            __syncthreads();
#pragma unroll 8
            for (int kk = 0; kk < KC; kk++) {
                float2 xv = *(const float2*)&buf0[(kc0 + kk) * 64 + pl];
                u64 x0 = pack2dup(xv.x);
                u64 x1d = pack2dup(xv.y);
#pragma unroll
                for (int j = 0; j < 12; j++) {
                    u64 w2 = *(const u64*)&wv[kk * 194 + c0 + 2 * j];
                    vacc[0][j] = ffma2(w2, x0, vacc[0][j]);
                    vacc[1][j] = ffma2(w2, x1d, vacc[1][j]);
                }
            }
        }
        __syncthreads();   // all xs reads done -> can overwrite with vt

        // ---- write V tile: vt[t][c] stride 194 (aliases xs region) ----
#pragma unroll
        for (int j = 0; j < 12; j++) {
            *(u64*)&buf0[(pl)     * 194 + c0 + 2 * j] = vacc[0][j];
            *(u64*)&buf0[(pl + 1) * 194 + c0 + 2 * j] = vacc[1][j];
        }
        __syncthreads();

        // ---- vsum (warps 0..2, packed, single owner per channel pair) ----
        if (tid < 96) {
            u64 sv = 0ull;
#pragma unroll 8
            for (int t = 0; t < SUB; t++)
                sv = fadd2(sv, *(const u64*)&buf0[t * 194 + 2 * tid]);
            float lo, hi; unpack2(sv, lo, hi);
            vsuml[2 * tid]     += lo;
            vsuml[2 * tid + 1] += hi;
        }

        // ---- matrix += Kn * V^T ----
#pragma unroll 2
        for (int t = 0; t < SUB; t++) {
            u64 kd[4];
#pragma unroll
            for (int i = 0; i < 4; i++)
                kd[i] = pack2dup(kn[(wgrp + 8 * i) * 64 + t]);
#pragma unroll
            for (int j = 0; j < 3; j++) {
                u64 v2 = *(const u64*)&buf0[t * 194 + pl + 64 * j];
#pragma unroll
                for (int i = 0; i < 4; i++)
                    macc[i][j] = ffma2(kd[i], v2, macc[i][j]);
            }
        }
    }

    __syncthreads();
    // ---- write per-block partials (deterministic) ----
    float* pm = g_part_mat + ((size_t)b * NPARTS + part) * CQ * C;
#pragma unroll
    for (int i = 0; i < 4; i++)
#pragma unroll
        for (int j = 0; j < 3; j++)
            *(u64*)&pm[(wgrp + 8 * i) * C + pl + 64 * j] = macc[i][j];
    if (tid < 192) g_part_vsum[((size_t)b * NPARTS + part) * C  + tid] = vsuml[tid];
    if (tid < 32)  g_part_ksum[((size_t)b * NPARTS + part) * CQ + tid] = ksuml[tid];
}

// =============================================================================
// Reduce partials (fixed order => deterministic)
// =============================================================================
__global__ void reduce_kernel()
{
    const int MATN = BATCH * CQ * C;
    const int VSN  = BATCH * C;
    const int KSN  = BATCH * CQ;
    int idx = blockIdx.x * blockDim.x + threadIdx.x;
    if (idx < MATN) {
        int bb = idx / (CQ * C), r = idx % (CQ * C);
        const float* p = g_part_mat + (size_t)bb * NPARTS * CQ * C + r;
        float sv = 0.f;
#pragma unroll 8
        for (int q = 0; q < NPARTS; q++) sv += p[(size_t)q * CQ * C];
        g_mat[idx] = sv;
    } else if (idx < MATN + VSN) {
        int k = idx - MATN;
        int bb = k / C, r = k % C;
        const float* p = g_part_vsum + (size_t)bb * NPARTS * C + r;
        float sv = 0.f;
#pragma unroll 8
        for (int q = 0; q < NPARTS; q++) sv += p[q * C];
        g_vsum[k] = sv;
    } else if (idx < MATN + VSN + KSN) {
        int k = idx - MATN - VSN;
        int bb = k / CQ, r = k % CQ;
        const float* p = g_part_ksum + (size_t)bb * NPARTS * CQ + r;
        float sv = 0.f;
#pragma unroll 8
        for (int q = 0; q < NPARTS; q++) sv += p[q * CQ];
        g_ksum[k] = sv;
    }
}

// =============================================================================
// Pass 2
// =============================================================================
__global__ __launch_bounds__(256, 2)
void pass2_kernel(const float* __restrict__ x1,
                  const float* __restrict__ Wq, const float* __restrict__ bq,
                  const float* __restrict__ gamma, float* __restrict__ out)
{
    extern __shared__ float sm[];
    float* xs     = sm + P2_XS;
    float* mats   = sm + P2_MATS;
    float* qn     = sm + P2_QN;
    float* qsq    = sm + P2_QSQ;
    float* invn   = sm + P2_INVN;
    float* sdp    = sm + P2_SDP;
    float* ts_s   = sm + P2_TS;
    float* ksum_s = sm + P2_KSUM;
    float* vsum_s = sm + P2_VSUM;

    const int tid  = threadIdx.x;
    const int lane = tid & 31;
    const int wgrp = tid >> 5;
    const int b    = blockIdx.y;
    const int part = blockIdx.x;
    const int pl   = 2 * lane;
    const int c0   = wgrp * 24;
    const float gm = gamma[0];

#pragma unroll
    for (int i = 0; i < 24; i++)
        mats[tid + i * 256] = g_mat[(size_t)b * CQ * C + tid + i * 256];
    if (tid < 32)  ksum_s[tid] = g_ksum[b * CQ + tid] + 1e-6f;
    if (tid < 192) vsum_s[tid] = g_vsum[b * C + tid];

    const float* x1b = x1 + (size_t)b * C * NPIX;
    float* outb = out + (size_t)b * C * NPIX;

    for (int s = 0; s < NSUBT; s++) {
        const int n0 = part * TILE + s * SUB;
        __syncthreads();
#pragma unroll
        for (int i = 0; i < 24; i++) {
            int c = wgrp + 8 * i;
            *(float2*)&xs[c * 64 + pl] =
                *(const float2*)&x1b[(size_t)c * NPIX + n0 + pl];
        }
        __syncthreads();

        // ---- Q projection (packed over pixel pair) ----
        u64 acc2[4];
#pragma unroll
        for (int u = 0; u < 4; u++) acc2[u] = pack2dup(bq[wgrp + 8 * u]);
        // Wq staged to mats? mats busy — read Wq through L1 here would regress;
        // instead stage Wq into qn region? qn needed. Use read-only global:
        // NOTE: stage Wq into a dedicated smem reuse of qsq/sdp is too small.
        // Wq is only 24KB of L2-resident data shared by all blocks; per-k loads
        // below are broadcast (lane-invariant) -> 4 LDG/k, L1-resident.
#pragma unroll 8
        for (int k = 0; k < C; k++) {
            u64 xp = *(const u64*)&xs[k * 64 + pl];
#pragma unroll
            for (int u = 0; u < 4; u++)
                acc2[u] = ffma2(xp, pack2dup(__ldg(&Wq[(wgrp + 8 * u) * C + k])), acc2[u]);
        }
        {
            u64 sq = fmul2(acc2[0], acc2[0]);
#pragma unroll
            for (int u = 1; u < 4; u++) sq = ffma2(acc2[u], acc2[u], sq);
            *(u64*)&qsq[wgrp * 64 + pl] = sq;
        }
        __syncthreads();
        if (tid < 64) {
            float tot = 0.f;
#pragma unroll
            for (int g = 0; g < 8; g++) tot += qsq[g * 64 + tid];
            invn[tid] = rsqrtf(tot);
        }
        __syncthreads();
        {
            u64 inv2 = *(const u64*)&invn[pl];
            u64 sd2 = 0ull;
#pragma unroll
            for (int u = 0; u < 4; u++) {
                u64 qp = fmul2(acc2[u], inv2);
                *(u64*)&qn[(wgrp + 8 * u) * 64 + pl] = qp;
                sd2 = ffma2(qp, pack2dup(ksum_s[wgrp + 8 * u]), sd2);
            }
            *(u64*)&sdp[wgrp * 64 + pl] = sd2;
        }
        __syncthreads();
        if (tid < 64) {
            float tot = 0.f;
#pragma unroll
            for (int g = 0; g < 8; g++) tot += sdp[g * 64 + tid];
            ts_s[tid] = 1.0f / (16384.0f + tot);
        }
        __syncthreads();

        // ---- out GEMM: 2 px x 12 ch-pairs per thread ----
        u64 oacc[2][12];
#pragma unroll
        for (int j = 0; j < 12; j++) {
            u64 vp = *(const u64*)&vsum_s[c0 + 2 * j];
            oacc[0][j] = vp; oacc[1][j] = vp;
        }
#pragma unroll 4
        for (int m = 0; m < CQ; m++) {
            float2 qq = *(const float2*)&qn[m * 64 + pl];
            u64 q0 = pack2dup(qq.x);
            u64 q1 = pack2dup(qq.y);
#pragma unroll
            for (int j = 0; j < 12; j++) {
                u64 w2 = *(const u64*)&mats[m * C + c0 + 2 * j];
                oacc[0][j] = ffma2(w2, q0, oacc[0][j]);
                oacc[1][j] = ffma2(w2, q1, oacc[1][j]);
            }
        }
        {
            float2 tss = *(const float2*)&ts_s[pl];
            u64 g0 = pack2dup(gm * tss.x);
            u64 g1 = pack2dup(gm * tss.y);
#pragma unroll
            for (int j = 0; j < 12; j++) {
                u64 o0 = fmul2(oacc[0][j], g0);
                u64 o1 = fmul2(oacc[1][j], g1);
                float a0, a1, b0, b1;
                unpack2(o0, a0, a1);
                unpack2(o1, b0, b1);
                // coalesced STG.64: {px0, px1} contiguous per channel
                *(float2*)&outb[(size_t)(c0 + 2 * j)     * NPIX + n0 + pl] =
                    make_float2(a0, b0);
                *(float2*)&outb[(size_t)(c0 + 2 * j + 1) * NPIX + n0 + pl] =
                    make_float2(a1, b1);
            }
        }
    }
}

// =============================================================================
extern "C" void kernel_launch(void* const* d_in, const int* in_sizes, int n_in,
                              void* d_out, int out_size)
{
    const float* x     = (const float*)d_in[0];
    const float* x1    = (const float*)d_in[1];
    const float* Wq    = (const float*)d_in[2];
    const float* bq    = (const float*)d_in[3];
    const float* Wk    = (const float*)d_in[4];
    const float* bk    = (const float*)d_in[5];
    const float* Wv    = (const float*)d_in[6];
    const float* bv    = (const float*)d_in[7];
    const float* gamma = (const float*)d_in[8];
    float* out = (float*)d_out;

    cudaFuncSetAttribute(pass1_kernel,
                         cudaFuncAttributeMaxDynamicSharedMemorySize, SMEM1_BYTES);
    cudaFuncSetAttribute(pass2_kernel,
                         cudaFuncAttributeMaxDynamicSharedMemorySize, SMEM2_BYTES);

    dim3 grid(NPARTS, BATCH);
    pass1_kernel<<<grid, 256, SMEM1_BYTES>>>(x, x1, Wk, bk, Wv, bv);

    const int RED = BATCH * CQ * C + BATCH * C + BATCH * CQ;
    reduce_kernel<<<(RED + 255) / 256, 256>>>();

    pass2_kernel<<<grid, 256, SMEM2_BYTES>>>(x1, Wq, bq, gamma, out);
}